// round 16
// baseline (speedup 1.0000x reference)
#include <cuda_runtime.h>
#include <stdint.h>

// FullPairwise (non-PBC), output float32 concat:
//   [0    , 2MP)  atom_index12  (row0 = i + m*N, row1 = j + m*N)
//   [2MP  , 5MP)  shift_values  (zeros, [MP,3])
//   [5MP  , 6MP)  mask          (d2 <= cutoff^2 as 0/1; NaN coords -> 0)
// MP = M*P, P = N*(N-1)/2, triu(k=1) row-major pair order.
//
// G-row tiling: one block owns G=4 consecutive triu rows; the interior loop
// loads each j-coordinate ONCE (coalesced LDG.128) and emits idx0/idx1/mask
// for all 4 rows (12 coalesced STG.32). Within-tile diagonal pairs are a
// 6-thread prologue. Tile t paired with T-1-t for constant per-block work.

#define MAX_ATOMS 16384
#define G 4
__device__ float4 g_coords4[MAX_ATOMS];

__global__ void pack_coords(const int* __restrict__ species,
                            const float* __restrict__ coords, int total) {
    int a = blockIdx.x * blockDim.x + threadIdx.x;
    if (a < total) {
        float x = coords[3 * a + 0];
        float y = coords[3 * a + 1];
        float z = coords[3 * a + 2];
        if (species[a] == -1) {
            x = __int_as_float(0x7fc00000);  // NaN -> mask false (matches ref)
            y = x; z = x;
        }
        g_coords4[a] = make_float4(x, y, z, 0.0f);
    }
}

__device__ __forceinline__ float mask1(float cix, float ciy, float ciz,
                                       float4 cj, float c2) {
    float dx = __fsub_rn(cix, cj.x);
    float dy = __fsub_rn(ciy, cj.y);
    float dz = __fsub_rn(ciz, cj.z);
    float d2 = __fadd_rn(__fadd_rn(__fmul_rn(dx, dx), __fmul_rn(dy, dy)),
                         __fmul_rn(dz, dz));
    return (d2 <= c2) ? 1.0f : 0.0f;
}

__device__ __forceinline__ void st_cs(float* p, float v) {
    asm volatile("st.global.cs.f32 [%0], %1;" :: "l"(p), "f"(v) : "memory");
}
__device__ __forceinline__ void st_cs4(float4* p, float4 v) {
    asm volatile("st.global.cs.v4.f32 [%0], {%1,%2,%3,%4};"
                 :: "l"(p), "f"(v.x), "f"(v.y), "f"(v.z), "f"(v.w) : "memory");
}

__device__ __forceinline__ void do_tile(float* __restrict__ out, int m, int it,
                                        int N, int R, int P, int MP, float c2,
                                        int tx, int bs) {
    int i0 = it * G;
    const float4* __restrict__ cm4 = g_coords4 + m * N;
    int moff = m * N;

    float cix[G], ciy[G], ciz[G], fi[G];
    int q0[G];
    #pragma unroll
    for (int rr = 0; rr < G; rr++) {
        int r = i0 + rr;
        int rc = (r < R) ? r : (R - 1);          // clamp OOB coord read
        float4 c = cm4[rc];
        cix[rr] = c.x; ciy[rr] = c.y; ciz[rr] = c.z;
        fi[rr] = (float)(r + moff);
        int rowstart = r * (N - 1) - (r * (r - 1)) / 2;
        q0[rr] = m * P + rowstart - (r + 1);     // +j -> element offset in row
    }

    // prologue: within-tile diagonal pairs (G=4 -> 6 pairs, mapping hardcoded)
    if (tx < (G * (G - 1)) / 2) {
        int rr = (tx < 3) ? 0 : (tx < 5) ? 1 : 2;
        int dj = (tx < 3) ? (tx + 1) : (tx < 5) ? (tx - 1) : 3;
        int r = i0 + rr;
        int j = i0 + dj;
        if (r < R && j < N) {
            float4 c = cm4[j];
            int q = q0[rr] + j;
            st_cs(out + q, fi[rr]);
            st_cs(out + MP + q, (float)(j + moff));
            st_cs(out + 5 * MP + q, mask1(cix[rr], ciy[rr], ciz[rr], c, c2));
        }
    }

    // interior: j in [i0+G, N); all G rows are valid here (max r <= N-2)
    #pragma unroll 2
    for (int j = i0 + G + tx; j < N; j += bs) {
        float4 c = __ldg(cm4 + j);
        float fjv = (float)(j + moff);
        #pragma unroll
        for (int rr = 0; rr < G; rr++) {
            int q = q0[rr] + j;
            st_cs(out + q, fi[rr]);
            st_cs(out + MP + q, fjv);
            st_cs(out + 5 * MP + q, mask1(cix[rr], ciy[rr], ciz[rr], c, c2));
        }
    }
}

__global__ void __launch_bounds__(256)
fullpairwise_kernel(float* __restrict__ out,
                    int N, int T, int bpm, int P, int MP, float c2) {
    int bid = blockIdx.x;
    int b = bid % bpm;
    int m = bid / bpm;
    int t1 = b;
    int t2 = T - 1 - b;
    int R = N - 1;
    int tx = threadIdx.x, bs = blockDim.x;

    // ---- flat zeros region: 3MP floats, contiguous aligned slice per block ----
    {
        int Z = 3 * MP;
        int g = gridDim.x;
        int zc = ((Z + g - 1) / g + 3) & ~3;
        int s = bid * zc;
        int e = s + zc; if (e > Z) e = Z;
        if (s < e) {
            int zb = 2 * MP + s;
            int len = e - s;
            int h = (4 - (zb & 3)) & 3; if (h > len) h = len;
            if (tx < h) out[zb + tx] = 0.0f;
            int nv = (len - h) >> 2;
            float4* vp = (float4*)(out + zb + h);
            float4 z4 = make_float4(0.f, 0.f, 0.f, 0.f);
            #pragma unroll 4
            for (int k = tx; k < nv; k += bs) st_cs4(vp + k, z4);
            int t = h + 4 * nv + tx;
            if (t < len) out[zb + t] = 0.0f;
        }
    }

    do_tile(out, m, t1, N, R, P, MP, c2, tx, bs);
    if (t2 > t1)
        do_tile(out, m, t2, N, R, P, MP, c2, tx, bs);
}

extern "C" void kernel_launch(void* const* d_in, const int* in_sizes, int n_in,
                              void* d_out, int out_size) {
    const int*   species = (const int*)d_in[0];
    const float* coords  = (const float*)d_in[1];
    float* out = (float*)d_out;

    long long MN = in_sizes[0];                        // M * N
    long long Nm1 = (long long)out_size / (3 * MN);    // out_size = 3*M*N*(N-1)
    int N = (int)Nm1 + 1;
    int M = (int)(MN / N);
    int P  = (int)((long long)N * (N - 1) / 2);
    int MP = M * P;

    int total = (int)MN;
    pack_coords<<<(total + 255) / 256, 256>>>(species, coords, total);

    const float c = 5.2f;
    int R = N - 1;                   // number of triu rows
    int T = (R + G - 1) / G;         // row tiles per molecule
    int bpm = (T + 1) / 2;           // paired tiles per molecule
    int blocks = M * bpm;
    fullpairwise_kernel<<<blocks, 256>>>(out, N, T, bpm, P, MP, c * c);
}

// round 17
// speedup vs baseline: 1.3760x; 1.3760x over previous
#include <cuda_runtime.h>
#include <stdint.h>

// FullPairwise (non-PBC), output float32 concat:
//   [0    , 2MP)  atom_index12  (row0 = i + m*N, row1 = j + m*N)
//   [2MP  , 5MP)  shift_values  (zeros, [MP,3])
//   [5MP  , 6MP)  mask          (d2 <= cutoff^2 as 0/1; NaN coords -> 0)
// MP = M*P, P = N*(N-1)/2, triu(k=1) row-major pair order.
//
// Block = paired rows (r1=b, r2=R-1-b): stores/block constant (3N).
// Shared j-range [r2+1, N) processed once with ONE coord load serving both
// rows. __stcs intrinsics (no asm barriers) let ptxas pipeline the loop.

#define MAX_ATOMS 16384
__device__ float4 g_coords4[MAX_ATOMS];

__global__ void pack_coords(const int* __restrict__ species,
                            const float* __restrict__ coords, int total) {
    int a = blockIdx.x * blockDim.x + threadIdx.x;
    if (a < total) {
        float x = coords[3 * a + 0];
        float y = coords[3 * a + 1];
        float z = coords[3 * a + 2];
        if (species[a] == -1) {
            x = __int_as_float(0x7fc00000);  // NaN -> mask false (matches ref)
            y = x; z = x;
        }
        g_coords4[a] = make_float4(x, y, z, 0.0f);
    }
}

__device__ __forceinline__ float mask1(float cix, float ciy, float ciz,
                                       float4 cj, float c2) {
    float dx = __fsub_rn(cix, cj.x);
    float dy = __fsub_rn(ciy, cj.y);
    float dz = __fsub_rn(ciz, cj.z);
    float d2 = __fadd_rn(__fadd_rn(__fmul_rn(dx, dx), __fmul_rn(dy, dy)),
                         __fmul_rn(dz, dz));
    return (d2 <= c2) ? 1.0f : 0.0f;
}

__global__ void __launch_bounds__(256)
fullpairwise_kernel(float* __restrict__ out,
                    int N, int bpm, int P, int MP, float c2) {
    int bid = blockIdx.x;
    int b = bid % bpm;
    int m = bid / bpm;
    int R = N - 1;
    int r1 = b;
    int r2 = R - 1 - b;
    int tx = threadIdx.x, bs = blockDim.x;

    // ---- flat zeros region: 3MP floats, contiguous aligned slice per block ----
    {
        int Z = 3 * MP;
        int g = gridDim.x;
        int zc = ((Z + g - 1) / g + 3) & ~3;
        int s = bid * zc;
        int e = s + zc; if (e > Z) e = Z;
        if (s < e) {
            int zb = 2 * MP + s;
            int len = e - s;
            int h = (4 - (zb & 3)) & 3; if (h > len) h = len;
            if (tx < h) out[zb + tx] = 0.0f;
            int nv = (len - h) >> 2;
            float4* vp = (float4*)(out + zb + h);
            float4 z4 = make_float4(0.f, 0.f, 0.f, 0.f);
            #pragma unroll 4
            for (int k = tx; k < nv; k += bs) __stcs(vp + k, z4);
            int t = h + 4 * nv + tx;
            if (t < len) out[zb + t] = 0.0f;
        }
    }

    const float4* __restrict__ cm4 = g_coords4 + m * N;
    int moff = m * N;

    float4 ca = cm4[r1];
    float4 cb = cm4[r2];
    float a_x = ca.x, a_y = ca.y, a_z = ca.z;
    float b_x = cb.x, b_y = cb.y, b_z = cb.z;
    float fi1 = (float)(r1 + moff);
    float fi2 = (float)(r2 + moff);
    float fmo = (float)moff;

    // element offset of pair (r, j) in a row region: q0r + j
    int q01 = m * P + r1 * (N - 1) - (r1 * (r1 - 1)) / 2 - (r1 + 1);
    int q02 = m * P + r2 * (N - 1) - (r2 * (r2 - 1)) / 2 - (r2 + 1);

    // ---- segment 1: j in [r1+1, r2+1)  (row r1 only) ----
    #pragma unroll 2
    for (int j = r1 + 1 + tx; j < r2 + 1; j += bs) {
        float4 c = __ldg(cm4 + j);
        int q = q01 + j;
        __stcs(out + q, fi1);
        __stcs(out + MP + q, fmo + (float)j);
        __stcs(out + 5 * MP + q, mask1(a_x, a_y, a_z, c, c2));
    }

    // ---- segment 2: j in [r2+1, N)  (both rows, one load) ----
    if (r2 > r1) {
        #pragma unroll 2
        for (int j = r2 + 1 + tx; j < N; j += bs) {
            float4 c = __ldg(cm4 + j);
            float fj = fmo + (float)j;
            int qa = q01 + j;
            int qb = q02 + j;
            __stcs(out + qa, fi1);
            __stcs(out + MP + qa, fj);
            __stcs(out + 5 * MP + qa, mask1(a_x, a_y, a_z, c, c2));
            __stcs(out + qb, fi2);
            __stcs(out + MP + qb, fj);
            __stcs(out + 5 * MP + qb, mask1(b_x, b_y, b_z, c, c2));
        }
    } else {
        // middle block when R is odd: single row r1, j in [r1+1, N)
        #pragma unroll 2
        for (int j = r2 + 1 + tx; j < N; j += bs) {
            float4 c = __ldg(cm4 + j);
            int q = q01 + j;
            __stcs(out + q, fi1);
            __stcs(out + MP + q, fmo + (float)j);
            __stcs(out + 5 * MP + q, mask1(a_x, a_y, a_z, c, c2));
        }
    }
}

extern "C" void kernel_launch(void* const* d_in, const int* in_sizes, int n_in,
                              void* d_out, int out_size) {
    const int*   species = (const int*)d_in[0];
    const float* coords  = (const float*)d_in[1];
    float* out = (float*)d_out;

    long long MN = in_sizes[0];                        // M * N
    long long Nm1 = (long long)out_size / (3 * MN);    // out_size = 3*M*N*(N-1)
    int N = (int)Nm1 + 1;
    int M = (int)(MN / N);
    int P  = (int)((long long)N * (N - 1) / 2);
    int MP = M * P;

    int total = (int)MN;
    pack_coords<<<(total + 255) / 256, 256>>>(species, coords, total);

    const float c = 5.2f;
    int R = N - 1;
    int bpm = (R + 1) / 2;
    int blocks = M * bpm;
    fullpairwise_kernel<<<blocks, 256>>>(out, N, bpm, P, MP, c * c);
}